// round 2
// baseline (speedup 1.0000x reference)
#include <cuda_runtime.h>
#include <math.h>

#define L_ 520
#define V_ 32128
#define R_ 512
#define KK 8                       // K = L - R
#define NROWS 9                    // logits rows 511..519 need softmax stats
#define NCHUNK 16
#define CHUNK4 502                 // float4s per chunk (502*4*16 = 32128)
#define V4 (V_ / 4)                // 8032
#define OUT_PROBS_OFF 521
#define TOTAL_ELEMS ((size_t)L_ * V_)                 // 16706560
#define OUT_TAIL (OUT_PROBS_OFF + TOTAL_ELEMS - 1)    // 16707080  (row519 col V-1)
#define OUT_NMATCH (OUT_PROBS_OFF + TOTAL_ELEMS)      // 16707081
// dst float4 index range for the aligned bulk copy:
#define Q_FIRST 131                                   // out elem 524
#define Q_LAST  4176769                               // out elems 16707076..79
#define NQ (Q_LAST - Q_FIRST + 1)                     // 4176639

struct Scratch {
    float pm[NROWS * NCHUNK];
    float ps[NROWS * NCHUNK];
    int   pa[NROWS * NCHUNK];
    float rmax[NROWS];
    float rsuminv[NROWS];
    int   rargmax[NROWS];
    int   n_match;
};
__device__ Scratch g_s;

// ---------------------------------------------------------------------------
// Kernel A: partial online-softmax stats. grid (9 rows, 16 chunks) x 256 thr.
// Single pass: per-thread online (m, argmax, sum_exp), then block tree-merge.
// ---------------------------------------------------------------------------
__device__ __forceinline__ void stat_merge(float& m1, int& a1, float& s1,
                                           float m2, int a2, float s2) {
    if (m2 > m1)       { s1 = s1 * expf(m1 - m2) + s2; m1 = m2; a1 = a2; }
    else if (m2 == m1) { s1 += s2; if (a2 < a1) a1 = a2; }
    else               { s1 += s2 * expf(m2 - m1); }
}

__global__ void partial_stats_kernel(const float* __restrict__ logits) {
    const int row = blockIdx.x;      // stats row i -> logits row 511+i
    const int chunk = blockIdx.y;
    const int tid = threadIdx.x;
    const float4* src = (const float4*)(logits + (size_t)(R_ - 1 + row) * V_)
                        + chunk * CHUNK4;

    float m = -INFINITY; int am = 0x7fffffff; float s = 0.f;
    for (int j = tid; j < CHUNK4; j += 256) {
        float4 v = src[j];
        int cb = (chunk * CHUNK4 + j) * 4;
        #pragma unroll
        for (int e = 0; e < 4; e++) {
            float x = (e == 0) ? v.x : (e == 1) ? v.y : (e == 2) ? v.z : v.w;
            if (x > m) { s = s * expf(m - x) + 1.f; m = x; am = cb + e; }
            else         s += expf(x - m);
        }
    }

    __shared__ float rm[256], rs[256];
    __shared__ int   ra[256];
    rm[tid] = m; rs[tid] = s; ra[tid] = am;
    __syncthreads();
    for (int off = 128; off > 0; off >>= 1) {
        if (tid < off) {
            float m1 = rm[tid], s1 = rs[tid]; int a1 = ra[tid];
            stat_merge(m1, a1, s1, rm[tid + off], ra[tid + off], rs[tid + off]);
            rm[tid] = m1; rs[tid] = s1; ra[tid] = a1;
        }
        __syncthreads();
    }
    if (tid == 0) {
        g_s.pm[row * NCHUNK + chunk] = rm[0];
        g_s.ps[row * NCHUNK + chunk] = rs[0];
        g_s.pa[row * NCHUNK + chunk] = ra[0];
    }
}

// ---------------------------------------------------------------------------
// Kernel B: merge partials, accept chain, ids, head/tail/nm scalars. 1 block.
// ---------------------------------------------------------------------------
__global__ void merge_decide_kernel(const void* __restrict__ ids_raw,
                                    const float* __restrict__ logits,
                                    const float* __restrict__ probs,
                                    float* __restrict__ out) {
    const int tid = threadIdx.x;
    __shared__ float sm_m[NROWS], sm_si[NROWS];
    __shared__ int   sm_a[NROWS];
    __shared__ int   s_nm;
    __shared__ int   s_flag;

    // int64-vs-int32 detection (all odd 32-bit words zero => int64 layout)
    const int* w = (const int*)ids_raw;
    if (tid == 0) s_flag = 0;
    __syncthreads();
    for (int j = 1 + 2 * tid; j < L_; j += 2 * blockDim.x)
        if (w[j] != 0) atomicOr(&s_flag, 1);

    // merge 16 partials per row (threads 0..8)
    if (tid < NROWS) {
        float m = -INFINITY, s = 0.f; int a = 0x7fffffff;
        #pragma unroll
        for (int c = 0; c < NCHUNK; c++)
            stat_merge(m, a, s, g_s.pm[tid * NCHUNK + c],
                       g_s.pa[tid * NCHUNK + c], g_s.ps[tid * NCHUNK + c]);
        float si = 1.0f / s;
        g_s.rmax[tid] = m; g_s.rsuminv[tid] = si; g_s.rargmax[tid] = a;
        sm_m[tid] = m; sm_si[tid] = si; sm_a[tid] = a;
    }
    __syncthreads();
    const int is64 = (s_flag == 0);
    const long long* w64 = (const long long*)ids_raw;

    if (tid == 0) {
        int d[KK]; float tl[KK], pp[KK];
        #pragma unroll
        for (int i = 0; i < KK; i++)
            d[i] = is64 ? (int)w64[R_ + i] : w[R_ + i];
        #pragma unroll
        for (int i = 0; i < KK; i++) {
            tl[i] = __ldg(&logits[(size_t)(R_ - 1 + i) * V_ + d[i]]);
            pp[i] = __ldg(&probs [(size_t)(R_ - 1 + i) * V_ + d[i]]);
        }
        int nm = 0; bool chain = true;
        #pragma unroll
        for (int i = 0; i < KK; i++) {
            float tp = expf(tl[i] - sm_m[i]) * sm_si[i];
            bool acc = (sm_a[i] == d[i]) || (tp > pp[i] * 0.5f);  // leniency=2
            if (chain && acc) nm++; else chain = false;
        }
        g_s.n_match = nm; s_nm = nm;
        out[OUT_NMATCH] = (float)nm;
        // tail element: out row 519, col V-1  (i_out = 7, logits row 518)
        out[OUT_TAIL] = (7 < nm)
            ? expf(__ldg(&logits[(size_t)518 * V_ + (V_ - 1)]) - sm_m[7]) * sm_si[7]
            : 0.f;
        // head elements: out row 0, cols 0..2 = probs[0..2]
        out[OUT_PROBS_OFF + 0] = probs[0];
        out[OUT_PROBS_OFF + 1] = probs[1];
        out[OUT_PROBS_OFF + 2] = probs[2];
    }
    __syncthreads();
    const int nm = s_nm;

    // id_res[0:512]
    for (int j = tid; j < R_; j += blockDim.x)
        out[j] = (float)(is64 ? (int)w64[j] : w[j]);
    // id_res[512:521]
    if (tid <= KK) {
        int pos = tid, v;
        if      (pos < nm)  v = is64 ? (int)w64[R_ + pos] : w[R_ + pos];
        else if (pos == nm) v = sm_a[pos];
        else                v = 0;
        out[R_ + pos] = (float)v;
    }
}

// ---------------------------------------------------------------------------
// Kernel C: aligned bulk write via warp-shuffle realignment.
// dst float4 q covers out[4q..4q+3] = src elems f..f+3, f = 4q-521 (≡3 mod 4).
// Source-aligned float4 a = q-130 covers f+1..f+4 and NEVER crosses a row
// boundary (V % 4 == 0), so its row is uniform; transformed .w is shuffled to
// lane+1, which is correct even for row-straddling dst float4s.
// ---------------------------------------------------------------------------
__device__ __forceinline__ float4 load_xform(const float4* __restrict__ probs4,
                                             const float4* __restrict__ logits4,
                                             unsigned a, int nm) {
    unsigned r = a / (unsigned)V4;          // compile-time magic-mul
    if (r < R_) return probs4[a];
    int i = (int)r - R_;
    if (i >= nm) { float4 z = {0.f, 0.f, 0.f, 0.f}; return z; }
    float m = g_s.rmax[i], si = g_s.rsuminv[i];
    float4 v = logits4[a - V4];             // logits row r-1
    float4 o;
    o.x = expf(v.x - m) * si; o.y = expf(v.y - m) * si;
    o.z = expf(v.z - m) * si; o.w = expf(v.w - m) * si;
    return o;
}

__global__ void bigout_kernel(const float4* __restrict__ probs4,
                              const float4* __restrict__ logits4,
                              float* __restrict__ out) {
    const int gid = blockIdx.x * blockDim.x + threadIdx.x;
    const int q = Q_FIRST + gid;
    const bool active = (q <= Q_LAST);
    const int lane = threadIdx.x & 31;
    const int nm = g_s.n_match;

    float4 A = {0.f, 0.f, 0.f, 0.f};
    if (active) A = load_xform(probs4, logits4, (unsigned)(q - 130), nm);

    float prevw = __shfl_up_sync(0xffffffffu, A.w, 1);
    if (lane == 0 && active) {
        float4 A0 = load_xform(probs4, logits4, (unsigned)(q - 131), nm);
        prevw = A0.w;
    }
    if (active) {
        float4 o; o.x = prevw; o.y = A.x; o.z = A.y; o.w = A.z;
        ((float4*)out)[q] = o;
    }
}

// ---------------------------------------------------------------------------
extern "C" void kernel_launch(void* const* d_in, const int* in_sizes, int n_in,
                              void* d_out, int out_size) {
    const float* logits = (const float*)d_in[0];
    const float* probs  = (const float*)d_in[1];
    const void*  ids    = d_in[2];
    float* out = (float*)d_out;

    dim3 gA(NROWS, NCHUNK);
    partial_stats_kernel<<<gA, 256>>>(logits);
    merge_decide_kernel<<<1, 256>>>(ids, logits, probs, out);
    int blocksC = (NQ + 255) / 256;
    bigout_kernel<<<blocksC, 256>>>((const float4*)probs, (const float4*)logits, out);
}

// round 4
// speedup vs baseline: 1.5553x; 1.5553x over previous
#include <cuda_runtime.h>
#include <math.h>

#define L_ 520
#define V_ 32128
#define R_ 512
#define KK 8                        // K = L - R
#define NROWS 9                     // logits rows 511..519 need stats
#define NCHUNK 16
#define CHUNK4 502                  // 502*4*16 = 32128
#define V4 (V_ / 4)                 // 8032
#define OUT_PROBS_OFF 521
#define TOTAL_ELEMS ((size_t)L_ * V_)                 // 16706560
#define OUT_TAIL (OUT_PROBS_OFF + TOTAL_ELEMS - 1)    // 16707080
#define OUT_NMATCH (OUT_PROBS_OFF + TOTAL_ELEMS)      // 16707081
// dst float4 q covers out[4q..4q+3]; src elem f = 4q-521 (f ≡ 3 mod 4)
#define Q_FIRST 131
#define QC_LAST 4112513             // last q entirely sourced from rows < 512
#define QT_FIRST 4112514
#define QT_LAST 4176769
#define STATS_BLOCKS 144            // 9 rows x 16 chunks
#define COPY_BLOCKS 4016            // ceil((QC_LAST-Q_FIRST+1)/(256*4))
#define COPY_STRIDE (COPY_BLOCKS * 256)
#define TAIL_BLOCKS 251             // (QT_LAST-QT_FIRST+1)/256 exactly

struct Scratch {
    float pm[NROWS * NCHUNK];
    float ps[NROWS * NCHUNK];
    int   pa[NROWS * NCHUNK];
    float rmax[NROWS];
    float rsuminv[NROWS];
    int   rargmax[NROWS];
    int   n_match;
};
__device__ Scratch g_s;
__device__ unsigned int g_cnt;      // zero-init; reset to 0 by merge block

__device__ __forceinline__ void stat_merge(float& m1, int& a1, float& s1,
                                           float m2, int a2, float s2) {
    if (m2 > m1)       { s1 = s1 * expf(m1 - m2) + s2; m1 = m2; a1 = a2; }
    else if (m2 == m1) { s1 += s2; if (a2 < a1) a1 = a2; }
    else               { s1 += s2 * expf(m2 - m1); }
}

// ---------------------------------------------------------------------------
// Launch 1: fused. bid < STATS_BLOCKS: online-softmax partials; the LAST
// finisher block (atomic counter, no spinning -> no deadlock risk) merges
// partials, runs the accept chain, and writes ids + scalars. All other blocks
// do the pure aligned copy of the rows<512 region via warp-shuffle
// realignment, 4 tasks/thread for MLP, streaming cache hints.
// ---------------------------------------------------------------------------
__global__ void __launch_bounds__(256) fused_kernel(
        const float* __restrict__ logits,
        const float* __restrict__ probs,
        const void*  __restrict__ ids_raw,
        float* __restrict__ out) {
    const int tid = threadIdx.x;

    if (blockIdx.x >= STATS_BLOCKS) {
        // ---------------- copy path ----------------
        const int t = (blockIdx.x - STATS_BLOCKS) * 256 + tid;
        const int lane = tid & 31;
        const float4* __restrict__ probs4 = (const float4*)probs;

        int q[4]; bool act[4]; float4 A[4];
        #pragma unroll
        for (int k = 0; k < 4; k++) {
            q[k] = Q_FIRST + k * COPY_STRIDE + t;
            act[k] = (q[k] <= QC_LAST);
        }
        #pragma unroll
        for (int k = 0; k < 4; k++)
            if (act[k]) A[k] = __ldcs(probs4 + (q[k] - 130));
        float pw[4];
        #pragma unroll
        for (int k = 0; k < 4; k++) {
            pw[k] = __shfl_up_sync(0xffffffffu, A[k].w, 1);
            if (lane == 0 && act[k])
                pw[k] = __ldcs(probs + (size_t)4 * q[k] - 521);
        }
        #pragma unroll
        for (int k = 0; k < 4; k++) {
            if (act[k]) {
                float4 o; o.x = pw[k]; o.y = A[k].x; o.z = A[k].y; o.w = A[k].z;
                __stcs(((float4*)out) + q[k], o);
            }
        }
        return;
    }

    // ---------------- stats path ----------------
    const int row = blockIdx.x >> 4;        // 0..8
    const int chunk = blockIdx.x & 15;      // 0..15
    const float4* src = (const float4*)(logits + (size_t)(R_ - 1 + row) * V_)
                        + chunk * CHUNK4;

    float m = -INFINITY; int am = 0x7fffffff; float s = 0.f;
    for (int j = tid; j < CHUNK4; j += 256) {
        float4 v = src[j];
        int cb = (chunk * CHUNK4 + j) * 4;
        #pragma unroll
        for (int e = 0; e < 4; e++) {
            float x = (e == 0) ? v.x : (e == 1) ? v.y : (e == 2) ? v.z : v.w;
            if (x > m) { s = s * expf(m - x) + 1.f; m = x; am = cb + e; }
            else         s += expf(x - m);
        }
    }
    __shared__ float rm[256], rs[256];
    __shared__ int   ra[256];
    rm[tid] = m; rs[tid] = s; ra[tid] = am;
    __syncthreads();
    for (int off = 128; off > 0; off >>= 1) {
        if (tid < off) {
            float m1 = rm[tid], s1 = rs[tid]; int a1 = ra[tid];
            stat_merge(m1, a1, s1, rm[tid + off], ra[tid + off], rs[tid + off]);
            rm[tid] = m1; rs[tid] = s1; ra[tid] = a1;
        }
        __syncthreads();
    }
    __shared__ int s_last;
    if (tid == 0) {
        g_s.pm[blockIdx.x] = rm[0];
        g_s.ps[blockIdx.x] = rs[0];
        g_s.pa[blockIdx.x] = ra[0];
        __threadfence();                    // release partials
        s_last = (atomicAdd(&g_cnt, 1u) == STATS_BLOCKS - 1) ? 1 : 0;
    }
    __syncthreads();
    if (!s_last) return;

    // -------- last stats block: merge + decide + ids --------
    __threadfence();                         // acquire partials
    __shared__ float sm_m[NROWS], sm_si[NROWS];
    __shared__ int   sm_a[NROWS];
    __shared__ int   s_nm, s_flag;
    const int* w = (const int*)ids_raw;
    if (tid == 0) s_flag = 0;
    __syncthreads();
    for (int j = 1 + 2 * tid; j < L_; j += 2 * 256)
        if (w[j] != 0) atomicOr(&s_flag, 1);

    if (tid < NROWS) {
        float mm = -INFINITY, ss = 0.f; int aa = 0x7fffffff;
        #pragma unroll
        for (int c = 0; c < NCHUNK; c++)
            stat_merge(mm, aa, ss, g_s.pm[tid * NCHUNK + c],
                       g_s.pa[tid * NCHUNK + c], g_s.ps[tid * NCHUNK + c]);
        float si = 1.0f / ss;
        g_s.rmax[tid] = mm; g_s.rsuminv[tid] = si; g_s.rargmax[tid] = aa;
        sm_m[tid] = mm; sm_si[tid] = si; sm_a[tid] = aa;
    }
    __syncthreads();
    const int is64 = (s_flag == 0);
    const long long* w64 = (const long long*)ids_raw;

    if (tid == 0) {
        int d[KK]; float tl[KK], pp[KK];
        #pragma unroll
        for (int i = 0; i < KK; i++)
            d[i] = is64 ? (int)w64[R_ + i] : w[R_ + i];
        #pragma unroll
        for (int i = 0; i < KK; i++) {
            tl[i] = __ldg(&logits[(size_t)(R_ - 1 + i) * V_ + d[i]]);
            pp[i] = __ldg(&probs [(size_t)(R_ - 1 + i) * V_ + d[i]]);
        }
        int nm = 0; bool chain = true;
        #pragma unroll
        for (int i = 0; i < KK; i++) {
            float tp = expf(tl[i] - sm_m[i]) * sm_si[i];
            bool acc = (sm_a[i] == d[i]) || (tp > pp[i] * 0.5f);  // leniency=2
            if (chain && acc) nm++; else chain = false;
        }
        g_s.n_match = nm; s_nm = nm;
        out[OUT_NMATCH] = (float)nm;
        out[OUT_TAIL] = (7 < nm)
            ? expf(__ldg(&logits[(size_t)518 * V_ + (V_ - 1)]) - sm_m[7]) * sm_si[7]
            : 0.f;
        out[OUT_PROBS_OFF + 0] = probs[0];
        out[OUT_PROBS_OFF + 1] = probs[1];
        out[OUT_PROBS_OFF + 2] = probs[2];
        g_cnt = 0;                            // reset for next graph replay
    }
    __syncthreads();
    const int nm = s_nm;
    for (int j = tid; j < R_; j += 256)
        out[j] = (float)(is64 ? (int)w64[j] : w[j]);
    if (tid <= KK) {
        int pos = tid, v;
        if      (pos < nm)  v = is64 ? (int)w64[R_ + pos] : w[R_ + pos];
        else if (pos == nm) v = sm_a[pos];
        else                v = 0;
        out[R_ + pos] = (float)v;
    }
}

// ---------------------------------------------------------------------------
// Launch 2: tail rows (masked softmax / zeros for out rows 512..519 + the
// straddle float4s near row 511/512 boundary). Shuffle realignment; each
// source-aligned float4 is row-uniform, so the shuffled .w is always correct.
// ---------------------------------------------------------------------------
__device__ __forceinline__ float4 load_xform(const float4* __restrict__ probs4,
                                             const float4* __restrict__ logits4,
                                             unsigned a, int nm) {
    unsigned r = a / (unsigned)V4;
    if (r < R_) return probs4[a];
    int i = (int)r - R_;
    if (i >= nm) { float4 z = {0.f, 0.f, 0.f, 0.f}; return z; }
    float m = g_s.rmax[i], si = g_s.rsuminv[i];
    float4 v = logits4[a - V4];
    float4 o;
    o.x = expf(v.x - m) * si; o.y = expf(v.y - m) * si;
    o.z = expf(v.z - m) * si; o.w = expf(v.w - m) * si;
    return o;
}

__global__ void __launch_bounds__(256) tail_kernel(
        const float4* __restrict__ probs4,
        const float4* __restrict__ logits4,
        float* __restrict__ out) {
    const int gid = blockIdx.x * 256 + threadIdx.x;
    const int q = QT_FIRST + gid;
    const int lane = threadIdx.x & 31;
    const int nm = g_s.n_match;

    float4 A = load_xform(probs4, logits4, (unsigned)(q - 130), nm);
    float prevw = __shfl_up_sync(0xffffffffu, A.w, 1);
    if (lane == 0)
        prevw = load_xform(probs4, logits4, (unsigned)(q - 131), nm).w;
    float4 o; o.x = prevw; o.y = A.x; o.z = A.y; o.w = A.z;
    ((float4*)out)[q] = o;
}

// ---------------------------------------------------------------------------
extern "C" void kernel_launch(void* const* d_in, const int* in_sizes, int n_in,
                              void* d_out, int out_size) {
    const float* logits = (const float*)d_in[0];
    const float* probs  = (const float*)d_in[1];
    const void*  ids    = d_in[2];
    float* out = (float*)d_out;

    fused_kernel<<<STATS_BLOCKS + COPY_BLOCKS, 256>>>(logits, probs, ids, out);
    tail_kernel<<<TAIL_BLOCKS, 256>>>((const float4*)probs,
                                      (const float4*)logits, out);
}